// round 1
// baseline (speedup 1.0000x reference)
#include <cuda_runtime.h>
#include <math.h>

#define B_SZ    8
#define T_LEN   4096
#define D_INP   128
#define D_OUTP  128
#define N_ST    256
#define L_CHUNK 32
#define CHUNKS  (T_LEN / L_CHUNK)   /* 128 */
#define NBLK    (B_SZ * CHUNKS)     /* 1024 */

typedef unsigned long long u64;

// ---------------- scratch (no allocations allowed) ----------------
__device__ float2 g_lam[N_ST];                    // lambda per channel
__device__ float2 g_lamL[N_ST];                   // lambda^L_CHUNK
__device__ float2 g_BcT[D_INP * N_ST];            // [k][n]  gamma*(B_re + i B_im), transposed
__device__ float2 g_CT [N_ST * D_OUTP];           // [n][d]  C transposed
__device__ float  g_DT [D_INP * D_OUTP];          // [k][d]  D transposed
__device__ float2 g_states[B_SZ * T_LEN * N_ST];  // local (then corrected-by-k2) states, 67MB
__device__ float2 g_carry [B_SZ * CHUNKS * N_ST]; // per-chunk carries

// ---------------- packed f32x2 helpers ----------------
__device__ __forceinline__ u64 pk2(float lo, float hi) {
    u64 r; asm("mov.b64 %0, {%1, %2};" : "=l"(r) : "f"(lo), "f"(hi)); return r;
}
__device__ __forceinline__ void upk2(u64 v, float& lo, float& hi) {
    asm("mov.b64 {%0, %1}, %2;" : "=f"(lo), "=f"(hi) : "l"(v));
}
__device__ __forceinline__ u64 fma2(u64 a, u64 b, u64 c) {
    u64 d; asm("fma.rn.f32x2 %0, %1, %2, %3;" : "=l"(d) : "l"(a), "l"(b), "l"(c)); return d;
}
__device__ __forceinline__ float2 cmul(float2 a, float2 b) {
    return make_float2(a.x * b.x - a.y * b.y, a.x * b.y + a.y * b.x);
}

// ---------------- kernel 0: parameter prep ----------------
__global__ void lru_prep(const float* __restrict__ nu_log,
                         const float* __restrict__ theta_log,
                         const float* __restrict__ gamma_log,
                         const float* __restrict__ B_re, const float* __restrict__ B_im,
                         const float* __restrict__ C_re, const float* __restrict__ C_im,
                         const float* __restrict__ Dm) {
    int idx = blockIdx.x * blockDim.x + threadIdx.x;   // 0 .. 32767
    if (idx < N_ST) {
        float la = expf(-expf(nu_log[idx]));
        float ph = expf(theta_log[idx]);
        float2 lam = make_float2(la * cosf(ph), la * sinf(ph));
        g_lam[idx] = lam;
        float2 p = lam;
        #pragma unroll
        for (int i = 0; i < 5; i++) p = cmul(p, p);     // lam^32 (L_CHUNK=32)
        g_lamL[idx] = p;
    }
    if (idx < D_INP * N_ST) {          // BcT[k][n] = gamma[n] * (B_re[n][k] + i B_im[n][k])
        int k = idx / N_ST, n = idx % N_ST;
        float g = expf(gamma_log[n]);
        g_BcT[idx] = make_float2(g * B_re[n * D_INP + k], g * B_im[n * D_INP + k]);
    }
    if (idx < N_ST * D_OUTP) {         // CT[n][d] = C[d][n]
        int n = idx / D_OUTP, d = idx % D_OUTP;
        g_CT[idx] = make_float2(C_re[d * N_ST + n], C_im[d * N_ST + n]);
    }
    if (idx < D_INP * D_OUTP) {        // DT[k][d] = D[d][k]
        int k = idx / D_OUTP, d = idx % D_OUTP;
        g_DT[idx] = Dm[d * D_INP + k];
    }
}

// ---------------- kernel 1: Bu = x @ BcT (complex) + local scan per chunk ----------------
// smem: bt (u64 [32][256], 64KB) | xs2 (u64 duplicated x [32][128], 32KB)  -> 96KB dyn
#define K1_SMEM (32 * N_ST * 8 + L_CHUNK * D_INP * 8)

__global__ __launch_bounds__(256) void lru_bu_scan(const float* __restrict__ x) {
    extern __shared__ char smem[];
    u64* bt  = (u64*)smem;                         // [kk][n] current k-tile of BcT (packed re,im)
    u64* xs2 = (u64*)(smem + 32 * N_ST * 8);       // [t][k]  (x, x) duplicated pairs

    int b = blockIdx.x / CHUNKS;
    int c = blockIdx.x % CHUNKS;
    int tid = threadIdx.x;
    int n = tid;

    // stage x chunk, duplicated into both halves of a 64-bit word
    const float* xp = x + (size_t)(b * T_LEN + c * L_CHUNK) * D_INP;
    #pragma unroll
    for (int i = 0; i < (L_CHUNK * D_INP) / 256; i++) {
        float v = xp[tid + i * 256];
        xs2[tid + i * 256] = pk2(v, v);
    }

    u64 acc[L_CHUNK];
    #pragma unroll
    for (int t = 0; t < L_CHUNK; t++) acc[t] = 0ULL;   // (0.f, 0.f)

    const u64* bsrc = (const u64*)g_BcT;
    for (int kt = 0; kt < D_INP / 32; kt++) {
        __syncthreads();   // also orders xs2 writes before first reads
        #pragma unroll
        for (int i = 0; i < (32 * N_ST) / 256; i++)
            bt[tid + i * 256] = bsrc[kt * 32 * N_ST + tid + i * 256];
        __syncthreads();
        #pragma unroll
        for (int kk = 0; kk < 32; kk++) {
            u64 b2 = bt[kk * N_ST + n];
            #pragma unroll
            for (int t = 0; t < L_CHUNK; t++) {
                acc[t] = fma2(xs2[t * D_INP + kt * 32 + kk], b2, acc[t]);
            }
        }
    }

    // sequential local scan (zero init), write local states + carry
    float2 lam = g_lam[n];
    float sre = 0.f, sim = 0.f;
    float2* sp = g_states + (size_t)(b * T_LEN + c * L_CHUNK) * N_ST + n;
    #pragma unroll
    for (int t = 0; t < L_CHUNK; t++) {
        float br, bi; upk2(acc[t], br, bi);
        float nr = fmaf(lam.x, sre, fmaf(-lam.y, sim, br));
        float ni = fmaf(lam.x, sim, fmaf( lam.y, sre, bi));
        sre = nr; sim = ni;
        sp[t * N_ST] = make_float2(sre, sim);
    }
    g_carry[(b * CHUNKS + c) * N_ST + n] = make_float2(sre, sim);
}

// ---------------- kernel 2: chunk-prefix fix + y = Re(states @ CT) + x @ DT ----------------
// smem: st (float2 [32][256], 64KB) | ct (u64 [32][128], 32KB, reused as float dt) | xs (float [32][128], 16KB)
#define K2_SMEM (L_CHUNK * N_ST * 8 + 32 * D_OUTP * 8 + L_CHUNK * D_INP * 4)

__global__ __launch_bounds__(256) void lru_fix_out(const float* __restrict__ x,
                                                   float* __restrict__ y) {
    extern __shared__ char smem[];
    float2* st = (float2*)smem;                                 // corrected states [t][n]
    u64*    ct = (u64*)(smem + L_CHUNK * N_ST * 8);             // C tile [nn][d] (packed)
    float*  xs = (float*)(smem + L_CHUNK * N_ST * 8 + 32 * D_OUTP * 8);

    int b = blockIdx.x / CHUNKS;
    int c = blockIdx.x % CHUNKS;
    int tid = threadIdx.x;

    // ---- phase A: per-channel prefix + correction (thread = channel n) ----
    {
        int n = tid;
        float2 lam  = g_lam[n];
        float2 lamL = g_lamL[n];
        float2 pre = make_float2(0.f, 0.f);
        const float2* cp = g_carry + b * CHUNKS * N_ST + n;
        for (int j = 0; j < c; j++) {                 // pre = lamL*pre + carry_j
            float2 cj = cp[j * N_ST];
            pre = cmul(lamL, pre);
            pre.x += cj.x; pre.y += cj.y;
        }
        float2 pw = lam;                               // lam^(t+1)
        const float2* sp = g_states + (size_t)(b * T_LEN + c * L_CHUNK) * N_ST + n;
        #pragma unroll
        for (int t = 0; t < L_CHUNK; t++) {
            float2 lv = sp[t * N_ST];
            float vr = lv.x + pw.x * pre.x - pw.y * pre.y;
            float vi = lv.y + pw.x * pre.y + pw.y * pre.x;
            st[t * N_ST + n] = make_float2(vr, vi);
            pw = cmul(pw, lam);
        }
        const float* xp = x + (size_t)(b * T_LEN + c * L_CHUNK) * D_INP;
        #pragma unroll
        for (int i = 0; i < (L_CHUNK * D_INP) / 256; i++)
            xs[tid + i * 256] = xp[tid + i * 256];
    }

    // ---- phase B: output GEMM. thread -> (tq, d); t = tq*16 + i ----
    int d  = tid & 127;
    int tq = tid >> 7;

    u64 acc[16];
    #pragma unroll
    for (int i = 0; i < 16; i++) acc[i] = 0ULL;

    const u64* csrc = (const u64*)g_CT;
    const u64* stu  = (const u64*)st;
    for (int nt = 0; nt < N_ST / 32; nt++) {
        __syncthreads();   // first pass: also orders phase-A writes before reads
        #pragma unroll
        for (int i = 0; i < (32 * D_OUTP) / 256; i++)
            ct[tid + i * 256] = csrc[nt * 32 * D_OUTP + tid + i * 256];
        __syncthreads();
        #pragma unroll
        for (int kk = 0; kk < 32; kk++) {
            u64 c2 = ct[kk * D_OUTP + d];
            int nn = nt * 32 + kk;
            #pragma unroll
            for (int i = 0; i < 16; i++) {
                // acc += (s_re*c_re , s_im*c_im) packed; Re() = lo - hi at the end
                acc[i] = fma2(stu[(tq * 16 + i) * N_ST + nn], c2, acc[i]);
            }
        }
    }
    float res[16];
    #pragma unroll
    for (int i = 0; i < 16; i++) { float a, bb; upk2(acc[i], a, bb); res[i] = a - bb; }

    // ---- x @ D.T term (scalar fp32; small fraction of flops) ----
    float* dt = (float*)ct;   // reuse C-tile buffer
    for (int kt = 0; kt < D_INP / 32; kt++) {
        __syncthreads();      // protect previous use of ct/dt
        #pragma unroll
        for (int i = 0; i < (32 * D_OUTP) / 256; i++)
            dt[tid + i * 256] = g_DT[kt * 32 * D_OUTP + tid + i * 256];
        __syncthreads();
        #pragma unroll
        for (int kk = 0; kk < 32; kk++) {
            float dv = dt[kk * D_OUTP + d];
            int k = kt * 32 + kk;
            #pragma unroll
            for (int i = 0; i < 16; i++)
                res[i] = fmaf(xs[(tq * 16 + i) * D_INP + k], dv, res[i]);
        }
    }

    float* yp = y + (size_t)(b * T_LEN + c * L_CHUNK) * D_OUTP + d;
    #pragma unroll
    for (int i = 0; i < 16; i++) yp[(tq * 16 + i) * D_OUTP] = res[i];
}

// ---------------- launch ----------------
extern "C" void kernel_launch(void* const* d_in, const int* in_sizes, int n_in,
                              void* d_out, int out_size) {
    (void)in_sizes; (void)n_in; (void)out_size;
    const float* x         = (const float*)d_in[0];
    const float* nu_log    = (const float*)d_in[1];
    const float* theta_log = (const float*)d_in[2];
    const float* gamma_log = (const float*)d_in[3];
    const float* B_re      = (const float*)d_in[4];
    const float* B_im      = (const float*)d_in[5];
    const float* C_re      = (const float*)d_in[6];
    const float* C_im      = (const float*)d_in[7];
    const float* Dm        = (const float*)d_in[8];
    float* y = (float*)d_out;

    cudaFuncSetAttribute(lru_bu_scan, cudaFuncAttributeMaxDynamicSharedMemorySize, K1_SMEM);
    cudaFuncSetAttribute(lru_fix_out, cudaFuncAttributeMaxDynamicSharedMemorySize, K2_SMEM);

    lru_prep<<<128, 256>>>(nu_log, theta_log, gamma_log, B_re, B_im, C_re, C_im, Dm);
    lru_bu_scan<<<NBLK, 256, K1_SMEM>>>(x);
    lru_fix_out<<<NBLK, 256, K2_SMEM>>>(x, y);
}

// round 2
// speedup vs baseline: 1.2544x; 1.2544x over previous
#include <cuda_runtime.h>
#include <math.h>

#define B_SZ    8
#define T_LEN   4096
#define D_INP   128
#define D_OUTP  128
#define N_ST    256
#define L_CHUNK 32
#define CHUNKS  (T_LEN / L_CHUNK)   /* 128 */
#define NBLK    (B_SZ * CHUNKS)     /* 1024 */

#define N_ROWS  320                 /* 256 state rows + 64 x-pair rows */
#define RPP     160                 /* rows per pass in k2 */
#define STRIDE  34                  /* padded t-stride for u64 smem rows */

typedef unsigned long long u64;

// ---------------- scratch ----------------
__device__ float2 g_lam[N_ST];
__device__ float2 g_lamL[N_ST];
__device__ float2 g_BcT[D_INP * N_ST];             // [k][n]
__device__ u64    g_CDT[N_ROWS * D_OUTP];          // [row][d]: rows<256 (Cre,Cim); rows>=256 (D[d][2kp], -D[d][2kp+1])
__device__ float2 g_states[B_SZ * T_LEN * N_ST];   // local states
__device__ float2 g_carry [B_SZ * CHUNKS * N_ST];
__device__ float2 g_pref  [B_SZ * CHUNKS * N_ST];  // exclusive chunk prefix

// ---------------- helpers ----------------
__device__ __forceinline__ u64 pk2(float lo, float hi) {
    u64 r; asm("mov.b64 %0, {%1, %2};" : "=l"(r) : "f"(lo), "f"(hi)); return r;
}
__device__ __forceinline__ void upk2(u64 v, float& lo, float& hi) {
    asm("mov.b64 {%0, %1}, %2;" : "=f"(lo), "=f"(hi) : "l"(v));
}
__device__ __forceinline__ u64 fma2(u64 a, u64 b, u64 c) {
    u64 d; asm("fma.rn.f32x2 %0, %1, %2, %3;" : "=l"(d) : "l"(a), "l"(b), "l"(c)); return d;
}
__device__ __forceinline__ float2 cmul(float2 a, float2 b) {
    return make_float2(a.x * b.x - a.y * b.y, a.x * b.y + a.y * b.x);
}

// ---------------- kernel 0: parameter prep ----------------
__global__ void lru_prep(const float* __restrict__ nu_log,
                         const float* __restrict__ theta_log,
                         const float* __restrict__ gamma_log,
                         const float* __restrict__ B_re, const float* __restrict__ B_im,
                         const float* __restrict__ C_re, const float* __restrict__ C_im,
                         const float* __restrict__ Dm) {
    int idx = blockIdx.x * blockDim.x + threadIdx.x;   // up to 40960
    if (idx < N_ST) {
        float la = expf(-expf(nu_log[idx]));
        float ph = expf(theta_log[idx]);
        float2 lam = make_float2(la * cosf(ph), la * sinf(ph));
        g_lam[idx] = lam;
        float2 p = lam;
        #pragma unroll
        for (int i = 0; i < 5; i++) p = cmul(p, p);     // lam^32
        g_lamL[idx] = p;
    }
    if (idx < D_INP * N_ST) {          // BcT[k][n]
        int k = idx / N_ST, n = idx % N_ST;
        float g = expf(gamma_log[n]);
        g_BcT[idx] = make_float2(g * B_re[n * D_INP + k], g * B_im[n * D_INP + k]);
    }
    if (idx < N_ROWS * D_OUTP) {       // extended C/D matrix [row][d]
        int r = idx / D_OUTP, d = idx % D_OUTP;
        if (r < N_ST) {
            g_CDT[idx] = pk2(C_re[d * N_ST + r], C_im[d * N_ST + r]);
        } else {
            int kp = r - N_ST;
            g_CDT[idx] = pk2(Dm[d * D_INP + 2 * kp], -Dm[d * D_INP + 2 * kp + 1]);
        }
    }
}

// ---------------- kernel 1: Bu = x @ BcT (complex) + local scan ----------------
// smem: bt u64[32][256] (64KB, reused as bu) | xsT u64[128][34] (34816B)
#define K1_SMEM (32 * N_ST * 8 + D_INP * STRIDE * 8)

__global__ __launch_bounds__(256, 2) void lru_bu_scan(const float* __restrict__ x) {
    extern __shared__ char smem[];
    u64* bt  = (u64*)smem;                          // [kk][n] tile of BcT / later bu [t][n]
    u64* xsT = (u64*)(smem + 32 * N_ST * 8);        // [k][t] duplicated (x,x) pairs, pad 34

    int b = blockIdx.x / CHUNKS;
    int c = blockIdx.x % CHUNKS;
    int tid = threadIdx.x;
    int h = tid >> 7;          // t-half: 0 or 1
    int j = tid & 127;         // n0 = j, n1 = j+128

    // stage x chunk transposed + duplicated
    const float* xp = x + (size_t)(b * T_LEN + c * L_CHUNK) * D_INP;
    #pragma unroll
    for (int i = 0; i < 16; i++) {
        int idx = tid + i * 256;           // t = idx>>7, k = idx&127
        float v = xp[idx];
        xsT[(idx & 127) * STRIDE + (idx >> 7)] = pk2(v, v);
    }

    u64 acc0[16], acc1[16];
    #pragma unroll
    for (int i = 0; i < 16; i++) { acc0[i] = 0ULL; acc1[i] = 0ULL; }

    const ulonglong2* bsrc = (const ulonglong2*)g_BcT;   // 2 u64 per ull2
    for (int kt = 0; kt < 4; kt++) {
        __syncthreads();
        #pragma unroll
        for (int i = 0; i < 16; i++)
            ((ulonglong2*)bt)[tid + i * 256] = bsrc[kt * 4096 + tid + i * 256];
        __syncthreads();
        #pragma unroll 8
        for (int kk = 0; kk < 32; kk++) {
            u64 b0 = bt[kk * N_ST + j];
            u64 b1 = bt[kk * N_ST + j + 128];
            const u64* xr = xsT + (kt * 32 + kk) * STRIDE + h * 16;
            #pragma unroll
            for (int tt = 0; tt < 8; tt++) {
                ulonglong2 xv = *(const ulonglong2*)(xr + 2 * tt);
                acc0[2 * tt]     = fma2(xv.x, b0, acc0[2 * tt]);
                acc0[2 * tt + 1] = fma2(xv.y, b0, acc0[2 * tt + 1]);
                acc1[2 * tt]     = fma2(xv.x, b1, acc1[2 * tt]);
                acc1[2 * tt + 1] = fma2(xv.y, b1, acc1[2 * tt + 1]);
            }
        }
    }

    // move Bu into smem (reuse bt) for the per-channel scan
    __syncthreads();
    u64* bu = bt;
    #pragma unroll
    for (int i = 0; i < 16; i++) {
        int t = h * 16 + i;
        bu[t * N_ST + j]       = acc0[i];
        bu[t * N_ST + j + 128] = acc1[i];
    }
    __syncthreads();

    // sequential local scan: thread = channel n
    int n = tid;
    float2 lam = g_lam[n];
    float sre = 0.f, sim = 0.f;
    float2* sp = g_states + (size_t)(b * T_LEN + c * L_CHUNK) * N_ST + n;
    #pragma unroll
    for (int t = 0; t < L_CHUNK; t++) {
        float br, bi; upk2(bu[t * N_ST + n], br, bi);
        float nr = fmaf(lam.x, sre, fmaf(-lam.y, sim, br));
        float ni = fmaf(lam.x, sim, fmaf( lam.y, sre, bi));
        sre = nr; sim = ni;
        sp[t * N_ST] = make_float2(sre, sim);
    }
    g_carry[(b * CHUNKS + c) * N_ST + n] = make_float2(sre, sim);
}

// ---------------- kernel 1b: exclusive prefix over chunk carries ----------------
__global__ void lru_prefix() {
    int b = blockIdx.x;           // 8 blocks
    int n = threadIdx.x;          // 256 threads
    float2 lamL = g_lamL[n];
    float2 pre = make_float2(0.f, 0.f);
    const float2* cp = g_carry + b * CHUNKS * N_ST + n;
    float2*       pp = g_pref  + b * CHUNKS * N_ST + n;
    for (int c = 0; c < CHUNKS; c++) {
        pp[c * N_ST] = pre;
        float2 cj = cp[c * N_ST];
        pre = cmul(lamL, pre);
        pre.x += cj.x; pre.y += cj.y;
    }
}

// ---------------- kernel 2: correction + y = Re(states @ C^T) + x @ D^T ----------------
// smem: stT u64[160][34] (43520B) | ct u64[32][128] (32KB)
#define K2_SMEM (RPP * STRIDE * 8 + 32 * D_OUTP * 8)

__global__ __launch_bounds__(128, 2) void lru_fix_out(const float* __restrict__ x,
                                                      float* __restrict__ y) {
    extern __shared__ char smem[];
    u64* stT = (u64*)smem;                              // [row_loc][t] pad 34
    u64* ct  = (u64*)(smem + RPP * STRIDE * 8);         // [kk][d]

    int b = blockIdx.x / CHUNKS;
    int c = blockIdx.x % CHUNKS;
    int tid = threadIdx.x;
    int h  = tid >> 6;          // t-half
    int dd = tid & 63;          // d0 = dd, d1 = dd+64

    u64 acc0[16], acc1[16];
    #pragma unroll
    for (int i = 0; i < 16; i++) { acc0[i] = 0ULL; acc1[i] = 0ULL; }

    for (int p = 0; p < 2; p++) {
        // ---- phase A: build stT rows [p*160, p*160+160) ----
        __syncthreads();
        for (int r = tid; r < RPP; r += 128) {
            int R = p * RPP + r;
            if (R < N_ST) {
                int n = R;
                float2 pre = g_pref[(b * CHUNKS + c) * N_ST + n];
                float2 lam = g_lam[n];
                float2 pw = lam;
                const float2* sp = g_states + (size_t)(b * T_LEN + c * L_CHUNK) * N_ST + n;
                #pragma unroll
                for (int t = 0; t < L_CHUNK; t++) {
                    float2 lv = sp[t * N_ST];
                    float vr = lv.x + pw.x * pre.x - pw.y * pre.y;
                    float vi = lv.y + pw.x * pre.y + pw.y * pre.x;
                    stT[r * STRIDE + t] = pk2(vr, vi);
                    pw = cmul(pw, lam);
                }
            } else {
                int kp = R - N_ST;
                const float* xp = x + (size_t)(b * T_LEN + c * L_CHUNK) * D_INP + 2 * kp;
                #pragma unroll
                for (int t = 0; t < L_CHUNK; t++)
                    stT[r * STRIDE + t] = *(const u64*)(xp + t * D_INP);
            }
        }
        __syncthreads();

        // ---- phase B: 5 row-tiles of 32 ----
        for (int nt = 0; nt < 5; nt++) {
            if (nt) __syncthreads();
            const ulonglong2* csrc = (const ulonglong2*)g_CDT;   // [R][d] pairs
            int base = (p * RPP + nt * 32) * 64;                 // in ull2 units (128 u64/row = 64 ull2)
            #pragma unroll
            for (int i = 0; i < 16; i++)
                ((ulonglong2*)ct)[tid + i * 128] = csrc[base + tid + i * 128];
            __syncthreads();
            #pragma unroll 8
            for (int kk = 0; kk < 32; kk++) {
                u64 c0 = ct[kk * D_OUTP + dd];
                u64 c1 = ct[kk * D_OUTP + dd + 64];
                const u64* sr = stT + (nt * 32 + kk) * STRIDE + h * 16;
                #pragma unroll
                for (int tt = 0; tt < 8; tt++) {
                    ulonglong2 sv = *(const ulonglong2*)(sr + 2 * tt);
                    acc0[2 * tt]     = fma2(sv.x, c0, acc0[2 * tt]);
                    acc0[2 * tt + 1] = fma2(sv.y, c0, acc0[2 * tt + 1]);
                    acc1[2 * tt]     = fma2(sv.x, c1, acc1[2 * tt]);
                    acc1[2 * tt + 1] = fma2(sv.y, c1, acc1[2 * tt + 1]);
                }
            }
        }
    }

    // epilogue: Re() = lo - hi  (D-term folded in via sign trick)
    float* yp = y + (size_t)(b * T_LEN + c * L_CHUNK + h * 16) * D_OUTP;
    #pragma unroll
    for (int i = 0; i < 16; i++) {
        float a0, b0, a1, b1;
        upk2(acc0[i], a0, b0);
        upk2(acc1[i], a1, b1);
        yp[i * D_OUTP + dd]      = a0 - b0;
        yp[i * D_OUTP + dd + 64] = a1 - b1;
    }
}

// ---------------- launch ----------------
extern "C" void kernel_launch(void* const* d_in, const int* in_sizes, int n_in,
                              void* d_out, int out_size) {
    (void)in_sizes; (void)n_in; (void)out_size;
    const float* x         = (const float*)d_in[0];
    const float* nu_log    = (const float*)d_in[1];
    const float* theta_log = (const float*)d_in[2];
    const float* gamma_log = (const float*)d_in[3];
    const float* B_re      = (const float*)d_in[4];
    const float* B_im      = (const float*)d_in[5];
    const float* C_re      = (const float*)d_in[6];
    const float* C_im      = (const float*)d_in[7];
    const float* Dm        = (const float*)d_in[8];
    float* y = (float*)d_out;

    cudaFuncSetAttribute(lru_bu_scan, cudaFuncAttributeMaxDynamicSharedMemorySize, K1_SMEM);
    cudaFuncSetAttribute(lru_fix_out, cudaFuncAttributeMaxDynamicSharedMemorySize, K2_SMEM);

    lru_prep<<<160, 256>>>(nu_log, theta_log, gamma_log, B_re, B_im, C_re, C_im, Dm);
    lru_bu_scan<<<NBLK, 256, K1_SMEM>>>(x);
    lru_prefix<<<B_SZ, N_ST>>>();
    lru_fix_out<<<NBLK, 128, K2_SMEM>>>(x, y);
}